// round 10
// baseline (speedup 1.0000x reference)
#include <cuda_runtime.h>
#include <cstdint>

// GatedBlockParity: N x 2048 fp32 in -> N x 1664 fp32 out
// in row:  [0,256) scalars | [256,640) gates (384) | [640,1408) ns1 (256x3) | [1408,2048) ns2 (128x5)
// out row: [0,256) relu(scalars) | [256,1024) ns1*sig(g1) | [1024,1664) ns2*sig(g2)

static constexpr int IN_W   = 2048;
static constexpr int OUT_W  = 1664;
static constexpr int OUT_W4 = OUT_W / 4;   // 416 float4 per row -> one thread each

__device__ __forceinline__ float sigmoidf_(float x) {
    return 1.0f / (1.0f + __expf(-x));
}

// One 416-thread block per FOUR rows {r, r+Q, r+2Q, r+3Q}.
// threadIdx.x == c4 directly; region boundaries (c4=64, c4=256) are
// warp-aligned -> zero divergence. The 4 data LDG.128s issue in the block
// prologue and remain outstanding across the barriered gate phase (MLP_p1=4).
// Gates: coalesced float4 fill into smem, sigmoid once, consumers do LDS.
__global__ __launch_bounds__(416) void gbp_kernel(const float* __restrict__ in,
                                                  float* __restrict__ out,
                                                  int rowsQ) {
    // 4 rows x 384 sigmoided gates, +8 pad for the provably-unused
    // i0+1 overread at the last ns2 group of row-block 3.
    __shared__ float sg[4 * 384 + 8];

    int row = blockIdx.x;
    int tid = threadIdx.x;
    int c   = tid << 2;

    const size_t istep = (size_t)rowsQ * IN_W;
    const size_t ostep = (size_t)rowsQ * OUT_W;
    const float* __restrict__ ir = in + (size_t)row * IN_W;
    float* __restrict__ orow = out + (size_t)row * OUT_W + c;

    // Region-dependent input offset (warp-uniform branch).
    int off;
    if (c < 256)       off = c;                   // scalars
    else if (c < 1024) off = 640  + (c - 256);    // ns1 data
    else               off = 1408 + (c - 1024);   // ns2 data

    // Front-batched streaming loads: latency overlaps the whole gate phase.
    float4 v0 = *reinterpret_cast<const float4*>(ir             + off);
    float4 v1 = *reinterpret_cast<const float4*>(ir +     istep + off);
    float4 v2 = *reinterpret_cast<const float4*>(ir + 2 * istep + off);
    float4 v3 = *reinterpret_cast<const float4*>(ir + 3 * istep + off);

    // Cooperative coalesced gate fill: 4 rows x 96 float4 = 384 loads.
    if (tid < 384) {
        int rk = tid / 96;            // which row of the 4
        int t  = tid - rk * 96;       // float4 index within the 384-gate row
        *reinterpret_cast<float4*>(&sg[rk * 384 + (t << 2)]) =
            *reinterpret_cast<const float4*>(ir + (size_t)rk * istep + 256 + (t << 2));
    }
    __syncthreads();

    // Sigmoid each gate exactly once: 1536 values, threads 0..383 do 4 each.
    if (tid < 384) {
        int k = tid << 2;
        sg[k]     = sigmoidf_(sg[k]);
        sg[k + 1] = sigmoidf_(sg[k + 1]);
        sg[k + 2] = sigmoidf_(sg[k + 2]);
        sg[k + 3] = sigmoidf_(sg[k + 3]);
    }
    __syncthreads();

    if (c < 256) {
        // scalars: relu
        v0.x = fmaxf(v0.x, 0.0f); v0.y = fmaxf(v0.y, 0.0f); v0.z = fmaxf(v0.z, 0.0f); v0.w = fmaxf(v0.w, 0.0f);
        v1.x = fmaxf(v1.x, 0.0f); v1.y = fmaxf(v1.y, 0.0f); v1.z = fmaxf(v1.z, 0.0f); v1.w = fmaxf(v1.w, 0.0f);
        v2.x = fmaxf(v2.x, 0.0f); v2.y = fmaxf(v2.y, 0.0f); v2.z = fmaxf(v2.z, 0.0f); v2.w = fmaxf(v2.w, 0.0f);
        v3.x = fmaxf(v3.x, 0.0f); v3.y = fmaxf(v3.y, 0.0f); v3.z = fmaxf(v3.z, 0.0f); v3.w = fmaxf(v3.w, 0.0f);
    } else if (c < 1024) {
        // ns1: 256 groups of 3; gates at sg[rk*384 + i]
        int j  = c - 256;
        int i0 = j / 3;
        int r  = j - 3 * i0;
        bool py = (r == 2), pz = (r >= 1);
        #define GATE1(V, BASE)  do {                                   \
            float s0 = sg[(BASE) + i0], s1 = sg[(BASE) + i0 + 1];      \
            V.x *= s0;                                                 \
            V.y *= py ? s1 : s0;                                       \
            V.z *= pz ? s1 : s0;                                       \
            V.w *= s1;                                                 \
        } while (0)
        GATE1(v0, 0); GATE1(v1, 384); GATE1(v2, 768); GATE1(v3, 1152);
        #undef GATE1
    } else {
        // ns2: 128 groups of 5; gates at sg[rk*384 + 256 + i]
        int j  = c - 1024;
        int i0 = j / 5;
        int r  = j - 5 * i0;
        bool py = (r == 4), pz = (r >= 3), pw = (r >= 2);
        #define GATE2(V, BASE)  do {                                   \
            float s0 = sg[(BASE) + 256 + i0];                          \
            float s1 = sg[(BASE) + 256 + i0 + 1]; /* i0=127: unused */ \
            V.x *= s0;                                                 \
            V.y *= py ? s1 : s0;                                       \
            V.z *= pz ? s1 : s0;                                       \
            V.w *= pw ? s1 : s0;                                       \
        } while (0)
        GATE2(v0, 0); GATE2(v1, 384); GATE2(v2, 768); GATE2(v3, 1152);
        #undef GATE2
    }

    *reinterpret_cast<float4*>(orow)             = v0;
    *reinterpret_cast<float4*>(orow +     ostep) = v1;
    *reinterpret_cast<float4*>(orow + 2 * ostep) = v2;
    *reinterpret_cast<float4*>(orow + 3 * ostep) = v3;
}

extern "C" void kernel_launch(void* const* d_in, const int* in_sizes, int n_in,
                              void* d_out, int out_size) {
    const float* in = (const float*)d_in[0];
    float* out = (float*)d_out;

    int n_rows = in_sizes[0] / IN_W;      // 65536 (divisible by 4)
    int rowsQ  = n_rows / 4;

    gbp_kernel<<<rowsQ, OUT_W4>>>(in, out, rowsQ);
}